// round 9
// baseline (speedup 1.0000x reference)
#include <cuda_runtime.h>
#include <cuda_fp16.h>

#define NN 50000
#define EE 1600000
#define GG 512
#define ETOT (EE + NN)
#define NB ((NN + 255) / 256)
#define HE (EE / 2)
#define GB1 ((NN + 63) / 64)
#define CVTB 16

// ---------------- scratch ----------------
__device__ __align__(16) __half g_W1h[128 * 128];
__device__ __align__(16) __half g_h1h[NN * 128];
__device__ float g_as1[NN * 4];
__device__ float g_ad1[NN * 4];
__device__ __align__(16) __half g_x2h[NN * 128];
__device__ __align__(16) __half g_h2h[NN * 32];
__device__ float g_as2[NN];
__device__ float g_ad2[NN];
__device__ int   g_deg[NN];          // starts 0; k_cls re-zeroes
__device__ int   g_rowptr[NN + 1];
__device__ int   g_pos[NN];
__device__ int   g_srcidx[ETOT];
__device__ int   g_boff[NB];
__device__ int   g_arrive;           // self-resets in k_blockscan
__device__ float g_pooled[GG * 32];
__device__ float g_cnt[GG];
__device__ int   g_is64;

__device__ __forceinline__ int idx_at(const void* p, int is64, long long i) {
  return is64 ? (int)((const long long*)p)[i] : ((const int*)p)[i];
}

// ---------------- count: dtype detect + degrees + self-loops + graph counts + cvtW ----------------
__global__ void k_count(const void* ei, const void* batch, const float* __restrict__ W1) {
  __shared__ int s64;
  if (threadIdx.x == 0) {
    const long long* p = (const long long*)ei;
    int ok = 1;
#pragma unroll
    for (int j = 0; j < 8; j++) {
      long long v = p[j];
      if (v < 0 || v >= NN) ok = 0;
    }
    s64 = ok;
    if (blockIdx.x == 0) g_is64 = ok;
  }
  __syncthreads();
  int is64 = s64;
  int i = blockIdx.x * blockDim.x + threadIdx.x;
  if (i < HE) {
    int d0, d1;
    if (is64) {
      longlong2 v = ((const longlong2*)((const long long*)ei + EE))[i];
      d0 = (int)v.x; d1 = (int)v.y;
    } else {
      int2 v = ((const int2*)((const int*)ei + EE))[i];
      d0 = v.x; d1 = v.y;
    }
    atomicAdd(&g_deg[d0], 1);
    atomicAdd(&g_deg[d1], 1);
  } else if (i < HE + NN) {
    int node = i - HE;
    atomicAdd(&g_deg[node], 1);
    atomicAdd(&g_cnt[idx_at(batch, is64, node)], 1.0f);
  } else {
    int j = i - (HE + NN);
    if (j < 128 * 128 / 4) {
      float4 v = ((const float4*)W1)[j];
      __half2 h0 = __floats2half2_rn(v.x, v.y);
      __half2 h1 = __floats2half2_rn(v.z, v.w);
      uint2 u;
      u.x = *(unsigned int*)&h0;
      u.y = *(unsigned int*)&h1;
      ((uint2*)g_W1h)[j] = u;
    }
  }
}

// ---------------- block sums + last-block exclusive scan ----------------
__global__ void k_blockscan() {
  __shared__ int ws[8];
  __shared__ int sm[256];
  __shared__ int isLast;
  int t = threadIdx.x, b = blockIdx.x;
  int i = b * 256 + t;
  int v = (i < NN) ? g_deg[i] : 0;
#pragma unroll
  for (int o = 16; o; o >>= 1) v += __shfl_down_sync(0xffffffffu, v, o);
  if ((t & 31) == 0) ws[t >> 5] = v;
  __syncthreads();
  if (t == 0) {
    int s = 0;
#pragma unroll
    for (int j = 0; j < 8; j++) s += ws[j];
    g_boff[b] = s;
    __threadfence();
    int old = atomicAdd(&g_arrive, 1);
    isLast = (old == NB - 1);
  }
  __syncthreads();
  if (!isLast) return;
  int vv = (t < NB) ? g_boff[t] : 0;
  sm[t] = vv;
  __syncthreads();
  for (int o = 1; o < 256; o <<= 1) {
    int u = (t >= o) ? sm[t - o] : 0;
    __syncthreads();
    sm[t] += u;
    __syncthreads();
  }
  if (t < NB) g_boff[t] = sm[t] - vv;
  if (t == 255) g_rowptr[NN] = sm[255];
  if (t == 0) g_arrive = 0;
}

__global__ void k_rowptr() {
  int t = threadIdx.x, b = blockIdx.x;
  int i = b * 256 + t;
  int v = (i < NN) ? g_deg[i] : 0;
  int lane = t & 31, w = t >> 5;
  int x = v;
#pragma unroll
  for (int o = 1; o < 32; o <<= 1) {
    int u = __shfl_up_sync(0xffffffffu, x, o);
    if (lane >= o) x += u;
  }
  __shared__ int ws[8], wo[8];
  if (lane == 31) ws[w] = x;
  __syncthreads();
  if (t == 0) {
    int r = 0;
#pragma unroll
    for (int j = 0; j < 8; j++) { wo[j] = r; r += ws[j]; }
  }
  __syncthreads();
  int off = g_boff[b] + wo[w] + x - v;
  if (i < NN) { g_rowptr[i] = off; g_pos[i] = off; }
}

__global__ void k_scatter(const void* ei) {
  int i = blockIdx.x * blockDim.x + threadIdx.x;
  int is64 = g_is64;
  if (i < HE) {
    int s0, s1, d0, d1;
    if (is64) {
      const long long* p = (const long long*)ei;
      longlong2 sv = ((const longlong2*)p)[i];
      longlong2 dv = ((const longlong2*)(p + EE))[i];
      s0 = (int)sv.x; s1 = (int)sv.y; d0 = (int)dv.x; d1 = (int)dv.y;
    } else {
      const int* p = (const int*)ei;
      int2 sv = ((const int2*)p)[i];
      int2 dv = ((const int2*)(p + EE))[i];
      s0 = sv.x; s1 = sv.y; d0 = dv.x; d1 = dv.y;
    }
    g_srcidx[atomicAdd(&g_pos[d0], 1)] = s0;
    g_srcidx[atomicAdd(&g_pos[d1], 1)] = s1;
  } else {
    int node = i - HE;
    if (node < NN) g_srcidx[atomicAdd(&g_pos[node], 1)] = node;
  }
}

// ---------------- layer1 linear via mma.sync ----------------
#define AS_STRIDE 40
#define BS_STRIDE 136
#define HS_STRIDE 132

__global__ __launch_bounds__(256) void k_gemm1(
    const float* __restrict__ x,
    const float* __restrict__ a_s, const float* __restrict__ a_d) {
  __shared__ __half As[64 * AS_STRIDE];
  __shared__ __half Bs[32 * BS_STRIDE];
  __shared__ __half Hs[64 * HS_STRIDE];
  int t = threadIdx.x;
  int lane = t & 31, wid = t >> 5;
  int warp_m = wid >> 1;
  int warp_n = wid & 1;
  int node0 = blockIdx.x * 64;

  float acc[8][4];
#pragma unroll
  for (int nt = 0; nt < 8; nt++)
#pragma unroll
    for (int j = 0; j < 4; j++) acc[nt][j] = 0.f;

  for (int c = 0; c < 4; c++) {
    int k0 = c * 32;
#pragma unroll
    for (int r = 0; r < 2; r++) {
      int i = t * 2 + r;
      int nd = i >> 3, kj = (i & 7) * 4;
      float4 v = (node0 + nd < NN)
          ? *(const float4*)&x[(long long)(node0 + nd) * 128 + k0 + kj]
          : make_float4(0.f, 0.f, 0.f, 0.f);
      __half2 h0 = __floats2half2_rn(v.x, v.y);
      __half2 h1 = __floats2half2_rn(v.z, v.w);
      uint2 u;
      u.x = *(unsigned int*)&h0;
      u.y = *(unsigned int*)&h1;
      *(uint2*)&As[nd * AS_STRIDE + kj] = u;
    }
#pragma unroll
    for (int r = 0; r < 4; r++) {
      int i = t * 4 + r;
      int kr = i >> 5, c4 = (i & 31) * 4;
      uint2 u = *(const uint2*)&g_W1h[(k0 + kr) * 128 + c4];
      *(uint2*)&Bs[kr * BS_STRIDE + c4] = u;
    }
    __syncthreads();
#pragma unroll
    for (int kk = 0; kk < 32; kk += 16) {
      unsigned int a0, a1, a2, a3;
      {
        unsigned int addr = (unsigned int)__cvta_generic_to_shared(
            &As[(warp_m * 16 + (lane & 15)) * AS_STRIDE + kk + ((lane >> 4) << 3)]);
        asm volatile("ldmatrix.sync.aligned.m8n8.x4.shared.b16 {%0,%1,%2,%3}, [%4];"
                     : "=r"(a0), "=r"(a1), "=r"(a2), "=r"(a3) : "r"(addr));
      }
#pragma unroll
      for (int tp = 0; tp < 4; tp++) {
        unsigned int b0, b1, b2, b3;
        unsigned int addr = (unsigned int)__cvta_generic_to_shared(
            &Bs[(kk + (lane & 15)) * BS_STRIDE + warp_n * 64 + tp * 16 + ((lane >> 4) << 3)]);
        asm volatile("ldmatrix.sync.aligned.m8n8.x4.trans.shared.b16 {%0,%1,%2,%3}, [%4];"
                     : "=r"(b0), "=r"(b1), "=r"(b2), "=r"(b3) : "r"(addr));
        asm volatile("mma.sync.aligned.m16n8k16.row.col.f32.f16.f16.f32 "
                     "{%0,%1,%2,%3}, {%4,%5,%6,%7}, {%8,%9}, {%0,%1,%2,%3};"
                     : "+f"(acc[2 * tp][0]), "+f"(acc[2 * tp][1]),
                       "+f"(acc[2 * tp][2]), "+f"(acc[2 * tp][3])
                     : "r"(a0), "r"(a1), "r"(a2), "r"(a3), "r"(b0), "r"(b1));
        asm volatile("mma.sync.aligned.m16n8k16.row.col.f32.f16.f16.f32 "
                     "{%0,%1,%2,%3}, {%4,%5,%6,%7}, {%8,%9}, {%0,%1,%2,%3};"
                     : "+f"(acc[2 * tp + 1][0]), "+f"(acc[2 * tp + 1][1]),
                       "+f"(acc[2 * tp + 1][2]), "+f"(acc[2 * tp + 1][3])
                     : "r"(a0), "r"(a1), "r"(a2), "r"(a3), "r"(b2), "r"(b3));
      }
    }
    __syncthreads();
  }
#pragma unroll
  for (int nt = 0; nt < 8; nt++) {
    int c0 = warp_n * 64 + nt * 8 + (lane & 3) * 2;
    int r0 = warp_m * 16 + (lane >> 2);
    __half2 lo = __floats2half2_rn(acc[nt][0], acc[nt][1]);
    __half2 hi = __floats2half2_rn(acc[nt][2], acc[nt][3]);
    *(__half2*)&Hs[r0 * HS_STRIDE + c0] = lo;
    *(__half2*)&Hs[(r0 + 8) * HS_STRIDE + c0] = hi;
  }
  __syncthreads();
  float4 av = *(const float4*)&a_s[lane * 4];
  float4 dv = *(const float4*)&a_d[lane * 4];
#pragma unroll
  for (int j = 0; j < 8; j++) {
    int n = wid * 8 + j;
    int nd = node0 + n;
    uint2 u = *(uint2*)&Hs[n * HS_STRIDE + lane * 4];
    float2 f0 = __half22float2(*(const __half2*)&u.x);
    float2 f1 = __half22float2(*(const __half2*)&u.y);
    if (nd < NN) *(uint2*)&g_h1h[(long long)nd * 128 + lane * 4] = u;
    float ps = f0.x * av.x + f0.y * av.y + f1.x * av.z + f1.y * av.w;
    float pd = f0.x * dv.x + f0.y * dv.y + f1.x * dv.z + f1.y * dv.w;
#pragma unroll
    for (int o = 4; o > 0; o >>= 1) {
      ps += __shfl_xor_sync(0xffffffffu, ps, o);
      pd += __shfl_xor_sync(0xffffffffu, pd, o);
    }
    if ((lane & 7) == 0 && nd < NN) {
      g_as1[nd * 4 + (lane >> 3)] = ps;
      g_ad1[nd * 4 + (lane >> 3)] = pd;
    }
  }
}

// ---------------- layer1 fused softmax+aggregate: HFMA2 inner, den in prologue ----------------
__global__ __launch_bounds__(256) void k_agg1(const float* __restrict__ b1) {
  __shared__ int     sm_s[8][32];
  __shared__ __half2 sm_eh[8][4][36];   // [warp][head][edge], padded row (144B) for LDS.128
  int wip = threadIdx.x >> 5;
  int node = (blockIdx.x * blockDim.x + threadIdx.x) >> 5;
  int lane = threadIdx.x & 31;
  if (node >= NN) return;
  int beg = g_rowptr[node], end = g_rowptr[node + 1];
  float4 adv = *(const float4*)&g_ad1[node * 4];
  int head = lane >> 3;
  float acc0 = 0, acc1 = 0, acc2 = 0, acc3 = 0;
  float den0 = 0, den1 = 0, den2 = 0, den3 = 0;
  for (int base = beg; base < end; base += 32) {
    int i = base + lane;
    if (i < end) {
      int s = g_srcidx[i];
      float4 asv = *(const float4*)&g_as1[s * 4];
      float t0 = asv.x + adv.x; t0 = t0 > 0.f ? t0 : 0.2f * t0;
      float t1 = asv.y + adv.y; t1 = t1 > 0.f ? t1 : 0.2f * t1;
      float t2 = asv.z + adv.z; t2 = t2 > 0.f ? t2 : 0.2f * t2;
      float t3 = asv.w + adv.w; t3 = t3 > 0.f ? t3 : 0.2f * t3;
      float e0 = __expf(t0), e1 = __expf(t1), e2 = __expf(t2), e3 = __expf(t3);
      den0 += e0; den1 += e1; den2 += e2; den3 += e3;
      sm_s[wip][lane] = s;
      sm_eh[wip][0][lane] = __float2half2_rn(e0);   // splatted
      sm_eh[wip][1][lane] = __float2half2_rn(e1);
      sm_eh[wip][2][lane] = __float2half2_rn(e2);
      sm_eh[wip][3][lane] = __float2half2_rn(e3);
    }
    __syncwarp();
    int cnt = min(32, end - base);
    int k = 0;
    for (; k + 8 <= cnt; k += 8) {
      __half2 ha0 = __float2half2_rn(0.f);
      __half2 ha1 = ha0;
#pragma unroll
      for (int j = 0; j < 8; j += 4) {
        int4 ss = *(const int4*)&sm_s[wip][k + j];
        uint4 wv = *(const uint4*)&sm_eh[wip][head][k + j];
        __half2 w0 = *(__half2*)&wv.x;
        __half2 w1 = *(__half2*)&wv.y;
        __half2 w2 = *(__half2*)&wv.z;
        __half2 w3 = *(__half2*)&wv.w;
        uint2 u0 = *((const uint2*)(g_h1h + (long long)ss.x * 128) + lane);
        uint2 u1 = *((const uint2*)(g_h1h + (long long)ss.y * 128) + lane);
        uint2 u2 = *((const uint2*)(g_h1h + (long long)ss.z * 128) + lane);
        uint2 u3 = *((const uint2*)(g_h1h + (long long)ss.w * 128) + lane);
        ha0 = __hfma2(w0, *(__half2*)&u0.x, ha0);
        ha1 = __hfma2(w0, *(__half2*)&u0.y, ha1);
        ha0 = __hfma2(w1, *(__half2*)&u1.x, ha0);
        ha1 = __hfma2(w1, *(__half2*)&u1.y, ha1);
        ha0 = __hfma2(w2, *(__half2*)&u2.x, ha0);
        ha1 = __hfma2(w2, *(__half2*)&u2.y, ha1);
        ha0 = __hfma2(w3, *(__half2*)&u3.x, ha0);
        ha1 = __hfma2(w3, *(__half2*)&u3.y, ha1);
      }
      float2 f0 = __half22float2(ha0);
      float2 f1 = __half22float2(ha1);
      acc0 += f0.x; acc1 += f0.y; acc2 += f1.x; acc3 += f1.y;
    }
    for (; k < cnt; k++) {                        // fp32 scalar tail
      int s = sm_s[wip][k];
      float w = __half2float(__low2half(sm_eh[wip][head][k]));
      uint2 u = *((const uint2*)(g_h1h + (long long)s * 128) + lane);
      float2 f0 = __half22float2(*(const __half2*)&u.x);
      float2 f1 = __half22float2(*(const __half2*)&u.y);
      acc0 = fmaf(w, f0.x, acc0);
      acc1 = fmaf(w, f0.y, acc1);
      acc2 = fmaf(w, f1.x, acc2);
      acc3 = fmaf(w, f1.y, acc3);
    }
    __syncwarp();
  }
  // cross-lane den reduction (each lane accumulated its own edges' weights)
#pragma unroll
  for (int o = 16; o; o >>= 1) {
    den0 += __shfl_xor_sync(0xffffffffu, den0, o);
    den1 += __shfl_xor_sync(0xffffffffu, den1, o);
    den2 += __shfl_xor_sync(0xffffffffu, den2, o);
    den3 += __shfl_xor_sync(0xffffffffu, den3, o);
  }
  float den = head == 0 ? den0 : head == 1 ? den1 : head == 2 ? den2 : den3;
  float inv = 1.0f / den;
  int c0 = lane * 4;
  float v0 = acc0 * inv + b1[c0];
  float v1 = acc1 * inv + b1[c0 + 1];
  float v2 = acc2 * inv + b1[c0 + 2];
  float v3 = acc3 * inv + b1[c0 + 3];
  v0 = v0 > 0.f ? v0 : expm1f(v0);
  v1 = v1 > 0.f ? v1 : expm1f(v1);
  v2 = v2 > 0.f ? v2 : expm1f(v2);
  v3 = v3 > 0.f ? v3 : expm1f(v3);
  __half2 h0 = __floats2half2_rn(v0, v1);
  __half2 h1 = __floats2half2_rn(v2, v3);
  uint2 st;
  st.x = *(unsigned int*)&h0;
  st.y = *(unsigned int*)&h1;
  *((uint2*)(g_x2h + (long long)node * 128) + lane) = st;
}

// ---------------- layer2 linear ----------------
__global__ __launch_bounds__(256) void k_gemm2(
    const float* __restrict__ W2, const float* __restrict__ a_s,
    const float* __restrict__ a_d) {
  __shared__ float xsT2[128][36];
  int t = threadIdx.x;
  int node0 = blockIdx.x * 32;
  for (int i = t; i < 32 * 64; i += 256) {
    int m = i >> 6, k2 = i & 63;
    int nd = node0 + m;
    float2 f = (nd < NN)
        ? __half22float2(*((const __half2*)(g_x2h + (long long)nd * 128) + k2))
        : make_float2(0.f, 0.f);
    xsT2[2 * k2][m] = f.x;
    xsT2[2 * k2 + 1][m] = f.y;
  }
  __syncthreads();
  int c = t & 31;
  int g = t >> 5;
  float acc[4] = {0.f, 0.f, 0.f, 0.f};
#pragma unroll 8
  for (int k = 0; k < 128; k++) {
    float w = W2[k * 32 + c];
    float4 xv = *(const float4*)&xsT2[k][4 * g];
    acc[0] = fmaf(xv.x, w, acc[0]);
    acc[1] = fmaf(xv.y, w, acc[1]);
    acc[2] = fmaf(xv.z, w, acc[2]);
    acc[3] = fmaf(xv.w, w, acc[3]);
  }
  float asv = a_s[c], adv = a_d[c];
#pragma unroll
  for (int j = 0; j < 4; j++) {
    int nd = node0 + 4 * g + j;
    if (nd >= NN) continue;
    g_h2h[nd * 32 + c] = __float2half_rn(acc[j]);
    float ps = acc[j] * asv;
    float pd = acc[j] * adv;
#pragma unroll
    for (int o = 16; o > 0; o >>= 1) {
      ps += __shfl_xor_sync(0xffffffffu, ps, o);
      pd += __shfl_xor_sync(0xffffffffu, pd, o);
    }
    if (c == 0) { g_as2[nd] = ps; g_ad2[nd] = pd; }
  }
}

// ---------------- layer2 fused softmax+aggregate + pool (den in prologue) ----------------
__global__ __launch_bounds__(256) void k_agg2(const float* __restrict__ b2,
                                              const void* batch) {
  __shared__ int   sm_s[8][32];
  __shared__ float sm_e[8][32];
  int wip = threadIdx.x >> 5;
  int node = (blockIdx.x * blockDim.x + threadIdx.x) >> 5;
  int lane = threadIdx.x & 31;
  if (node >= NN) return;
  int beg = g_rowptr[node], end = g_rowptr[node + 1];
  float adv = g_ad2[node];
  float acc = 0.f, den = 0.f;
  for (int base = beg; base < end; base += 32) {
    int i = base + lane;
    if (i < end) {
      int s = g_srcidx[i];
      float a = g_as2[s] + adv;
      a = a > 0.f ? a : 0.2f * a;
      float e = __expf(a);
      den += e;
      sm_s[wip][lane] = s;
      sm_e[wip][lane] = e;
    }
    __syncwarp();
    int cnt = min(32, end - base);
    int k = 0;
    for (; k + 4 <= cnt; k += 4) {
      int4   ss = *(const int4*)&sm_s[wip][k];
      float4 ww = *(const float4*)&sm_e[wip][k];
      __half h0 = g_h2h[ss.x * 32 + lane];
      __half h1 = g_h2h[ss.y * 32 + lane];
      __half h2 = g_h2h[ss.z * 32 + lane];
      __half h3 = g_h2h[ss.w * 32 + lane];
      acc = fmaf(ww.x, __half2float(h0), acc);
      acc = fmaf(ww.y, __half2float(h1), acc);
      acc = fmaf(ww.z, __half2float(h2), acc);
      acc = fmaf(ww.w, __half2float(h3), acc);
    }
    for (; k < cnt; k++) {
      acc = fmaf(sm_e[wip][k], __half2float(g_h2h[sm_s[wip][k] * 32 + lane]), acc);
    }
    __syncwarp();
  }
#pragma unroll
  for (int o = 16; o; o >>= 1) den += __shfl_xor_sync(0xffffffffu, den, o);
  float v = acc / den + b2[lane];
  v = v > 0.f ? v : expm1f(v);
  int gph = idx_at(batch, g_is64, node);
  atomicAdd(&g_pooled[gph * 32 + lane], v);
}

// ---------------- classifier + state reset ----------------
__global__ void k_cls(const float* __restrict__ Wc1, const float* __restrict__ bc1,
                      const float* __restrict__ Wc2, const float* __restrict__ bc2,
                      float* __restrict__ out) {
  int i = blockIdx.x * blockDim.x + threadIdx.x;
  if (i < NN) g_deg[i] = 0;
  if (i >= GG) return;
  int g = i;
  float inv = 1.0f / g_cnt[g];
  float p[32];
#pragma unroll
  for (int c = 0; c < 32; c++) {
    p[c] = g_pooled[g * 32 + c] * inv;
    g_pooled[g * 32 + c] = 0.f;
  }
  g_cnt[g] = 0.f;
  float o = bc2[0];
#pragma unroll
  for (int j = 0; j < 16; j++) {
    float z = bc1[j];
#pragma unroll
    for (int c = 0; c < 32; c++) z = fmaf(p[c], Wc1[c * 16 + j], z);
    if (z > 0.f) o = fmaf(z, Wc2[j], o);
  }
  out[g] = o;
}

// ---------------- launch ----------------
extern "C" void kernel_launch(void* const* d_in, const int* in_sizes, int n_in,
                              void* d_out, int out_size) {
  const float* x   = (const float*)d_in[0];
  const void*  ei  = d_in[1];
  const void*  bat = d_in[3];
  const float* W1  = (const float*)d_in[4];
  const float* as1 = (const float*)d_in[5];
  const float* ad1 = (const float*)d_in[6];
  const float* b1  = (const float*)d_in[7];
  const float* W2  = (const float*)d_in[8];
  const float* as2 = (const float*)d_in[9];
  const float* ad2 = (const float*)d_in[10];
  const float* b2  = (const float*)d_in[11];
  const float* Wc1 = (const float*)d_in[12];
  const float* bc1 = (const float*)d_in[13];
  const float* Wc2 = (const float*)d_in[14];
  const float* bc2 = (const float*)d_in[15];
  float* out = (float*)d_out;

  k_count<<<(HE + NN + 255) / 256 + CVTB, 256>>>(ei, bat, W1);
  k_blockscan<<<NB, 256>>>();
  k_rowptr<<<NB, 256>>>();
  k_scatter<<<(HE + NN + 255) / 256, 256>>>(ei);   // 4th launch -> ncu window
  k_gemm1<<<GB1, 256>>>(x, as1, ad1);
  k_agg1<<<(NN * 32 + 255) / 256, 256>>>(b1);
  k_gemm2<<<(NN + 31) / 32, 256>>>(W2, as2, ad2);
  k_agg2<<<(NN * 32 + 255) / 256, 256>>>(b2, bat);
  k_cls<<<NB, 256>>>(Wc1, bc1, Wc2, bc2, out);
}

// round 10
// speedup vs baseline: 1.0562x; 1.0562x over previous
#include <cuda_runtime.h>
#include <cuda_fp16.h>

#define NN 50000
#define EE 1600000
#define GG 512
#define ETOT (EE + NN)
#define NB ((NN + 255) / 256)
#define HE (EE / 2)
#define GB1 ((NN + 63) / 64)
#define SCB ((HE + NN + 255) / 256)
#define CVTB 16

// ---------------- scratch ----------------
__device__ __align__(16) __half g_W1h[128 * 128];
__device__ __align__(16) __half g_h1h[NN * 128];
__device__ float g_as1[NN * 4];
__device__ float g_ad1[NN * 4];
__device__ __align__(16) __half g_x2h[NN * 128];
__device__ __align__(16) __half g_h2h[NN * 32];
__device__ float g_as2[NN];
__device__ float g_ad2[NN];
__device__ int   g_deg[NN];          // starts 0; k_cls re-zeroes
__device__ int   g_rowptr[NN + 1];
__device__ int   g_pos[NN];
__device__ int   g_srcidx[ETOT];
__device__ int   g_boff[NB];
__device__ int   g_arrive;           // self-resets in k_blockscan
__device__ float g_pooled[GG * 32];
__device__ float g_cnt[GG];
__device__ int   g_is64;

__device__ __forceinline__ int idx_at(const void* p, int is64, long long i) {
  return is64 ? (int)((const long long*)p)[i] : ((const int*)p)[i];
}

// ---------------- count: dtype detect + degrees + self-loops + graph counts + cvtW ----------------
__global__ void k_count(const void* ei, const void* batch, const float* __restrict__ W1) {
  __shared__ int s64;
  if (threadIdx.x == 0) {
    const long long* p = (const long long*)ei;
    int ok = 1;
#pragma unroll
    for (int j = 0; j < 8; j++) {
      long long v = p[j];
      if (v < 0 || v >= NN) ok = 0;
    }
    s64 = ok;
    if (blockIdx.x == 0) g_is64 = ok;
  }
  __syncthreads();
  int is64 = s64;
  int i = blockIdx.x * blockDim.x + threadIdx.x;
  if (i < HE) {
    int d0, d1;
    if (is64) {
      longlong2 v = ((const longlong2*)((const long long*)ei + EE))[i];
      d0 = (int)v.x; d1 = (int)v.y;
    } else {
      int2 v = ((const int2*)((const int*)ei + EE))[i];
      d0 = v.x; d1 = v.y;
    }
    atomicAdd(&g_deg[d0], 1);
    atomicAdd(&g_deg[d1], 1);
  } else if (i < HE + NN) {
    int node = i - HE;
    atomicAdd(&g_deg[node], 1);
    atomicAdd(&g_cnt[idx_at(batch, is64, node)], 1.0f);
  } else {
    int j = i - (HE + NN);
    if (j < 128 * 128 / 4) {
      float4 v = ((const float4*)W1)[j];
      __half2 h0 = __floats2half2_rn(v.x, v.y);
      __half2 h1 = __floats2half2_rn(v.z, v.w);
      uint2 u;
      u.x = *(unsigned int*)&h0;
      u.y = *(unsigned int*)&h1;
      ((uint2*)g_W1h)[j] = u;
    }
  }
}

// ---------------- block sums + last-block exclusive scan ----------------
__global__ void k_blockscan() {
  __shared__ int ws[8];
  __shared__ int sm[256];
  __shared__ int isLast;
  int t = threadIdx.x, b = blockIdx.x;
  int i = b * 256 + t;
  int v = (i < NN) ? g_deg[i] : 0;
#pragma unroll
  for (int o = 16; o; o >>= 1) v += __shfl_down_sync(0xffffffffu, v, o);
  if ((t & 31) == 0) ws[t >> 5] = v;
  __syncthreads();
  if (t == 0) {
    int s = 0;
#pragma unroll
    for (int j = 0; j < 8; j++) s += ws[j];
    g_boff[b] = s;
    __threadfence();
    int old = atomicAdd(&g_arrive, 1);
    isLast = (old == NB - 1);
  }
  __syncthreads();
  if (!isLast) return;
  int vv = (t < NB) ? g_boff[t] : 0;
  sm[t] = vv;
  __syncthreads();
  for (int o = 1; o < 256; o <<= 1) {
    int u = (t >= o) ? sm[t - o] : 0;
    __syncthreads();
    sm[t] += u;
    __syncthreads();
  }
  if (t < NB) g_boff[t] = sm[t] - vv;
  if (t == 255) g_rowptr[NN] = sm[255];
  if (t == 0) g_arrive = 0;
}

__global__ void k_rowptr() {
  int t = threadIdx.x, b = blockIdx.x;
  int i = b * 256 + t;
  int v = (i < NN) ? g_deg[i] : 0;
  int lane = t & 31, w = t >> 5;
  int x = v;
#pragma unroll
  for (int o = 1; o < 32; o <<= 1) {
    int u = __shfl_up_sync(0xffffffffu, x, o);
    if (lane >= o) x += u;
  }
  __shared__ int ws[8], wo[8];
  if (lane == 31) ws[w] = x;
  __syncthreads();
  if (t == 0) {
    int r = 0;
#pragma unroll
    for (int j = 0; j < 8; j++) { wo[j] = r; r += ws[j]; }
  }
  __syncthreads();
  int off = g_boff[b] + wo[w] + x - v;
  if (i < NN) { g_rowptr[i] = off; g_pos[i] = off; }
}

// ---------------- FUSED: gemm1 (blocks < GB1) + scatter (blocks >= GB1) ----------------
#define AS_STRIDE 40
#define BS_STRIDE 136
#define HS_STRIDE 132

__global__ __launch_bounds__(256) void k_gs(
    const float* __restrict__ x,
    const float* __restrict__ a_s, const float* __restrict__ a_d,
    const void* ei) {
  __shared__ __half As[64 * AS_STRIDE];
  __shared__ __half Bs[32 * BS_STRIDE];
  __shared__ __half Hs[64 * HS_STRIDE];

  if (blockIdx.x >= GB1) {
    // ----- scatter path (latency-bound; overlaps with gemm blocks) -----
    int i = (blockIdx.x - GB1) * 256 + threadIdx.x;
    int is64 = g_is64;
    if (i < HE) {
      int s0, s1, d0, d1;
      if (is64) {
        const long long* p = (const long long*)ei;
        longlong2 sv = ((const longlong2*)p)[i];
        longlong2 dv = ((const longlong2*)(p + EE))[i];
        s0 = (int)sv.x; s1 = (int)sv.y; d0 = (int)dv.x; d1 = (int)dv.y;
      } else {
        const int* p = (const int*)ei;
        int2 sv = ((const int2*)p)[i];
        int2 dv = ((const int2*)(p + EE))[i];
        s0 = sv.x; s1 = sv.y; d0 = dv.x; d1 = dv.y;
      }
      g_srcidx[atomicAdd(&g_pos[d0], 1)] = s0;
      g_srcidx[atomicAdd(&g_pos[d1], 1)] = s1;
    } else {
      int node = i - HE;
      if (node < NN) g_srcidx[atomicAdd(&g_pos[node], 1)] = node;
    }
    return;
  }

  // ----- gemm1 path (mma.sync) -----
  int t = threadIdx.x;
  int lane = t & 31, wid = t >> 5;
  int warp_m = wid >> 1;
  int warp_n = wid & 1;
  int node0 = blockIdx.x * 64;

  float acc[8][4];
#pragma unroll
  for (int nt = 0; nt < 8; nt++)
#pragma unroll
    for (int j = 0; j < 4; j++) acc[nt][j] = 0.f;

  for (int c = 0; c < 4; c++) {
    int k0 = c * 32;
#pragma unroll
    for (int r = 0; r < 2; r++) {
      int i = t * 2 + r;
      int nd = i >> 3, kj = (i & 7) * 4;
      float4 v = (node0 + nd < NN)
          ? *(const float4*)&x[(long long)(node0 + nd) * 128 + k0 + kj]
          : make_float4(0.f, 0.f, 0.f, 0.f);
      __half2 h0 = __floats2half2_rn(v.x, v.y);
      __half2 h1 = __floats2half2_rn(v.z, v.w);
      uint2 u;
      u.x = *(unsigned int*)&h0;
      u.y = *(unsigned int*)&h1;
      *(uint2*)&As[nd * AS_STRIDE + kj] = u;
    }
#pragma unroll
    for (int r = 0; r < 4; r++) {
      int i = t * 4 + r;
      int kr = i >> 5, c4 = (i & 31) * 4;
      uint2 u = *(const uint2*)&g_W1h[(k0 + kr) * 128 + c4];
      *(uint2*)&Bs[kr * BS_STRIDE + c4] = u;
    }
    __syncthreads();
#pragma unroll
    for (int kk = 0; kk < 32; kk += 16) {
      unsigned int a0, a1, a2, a3;
      {
        unsigned int addr = (unsigned int)__cvta_generic_to_shared(
            &As[(warp_m * 16 + (lane & 15)) * AS_STRIDE + kk + ((lane >> 4) << 3)]);
        asm volatile("ldmatrix.sync.aligned.m8n8.x4.shared.b16 {%0,%1,%2,%3}, [%4];"
                     : "=r"(a0), "=r"(a1), "=r"(a2), "=r"(a3) : "r"(addr));
      }
#pragma unroll
      for (int tp = 0; tp < 4; tp++) {
        unsigned int b0, b1, b2, b3;
        unsigned int addr = (unsigned int)__cvta_generic_to_shared(
            &Bs[(kk + (lane & 15)) * BS_STRIDE + warp_n * 64 + tp * 16 + ((lane >> 4) << 3)]);
        asm volatile("ldmatrix.sync.aligned.m8n8.x4.trans.shared.b16 {%0,%1,%2,%3}, [%4];"
                     : "=r"(b0), "=r"(b1), "=r"(b2), "=r"(b3) : "r"(addr));
        asm volatile("mma.sync.aligned.m16n8k16.row.col.f32.f16.f16.f32 "
                     "{%0,%1,%2,%3}, {%4,%5,%6,%7}, {%8,%9}, {%0,%1,%2,%3};"
                     : "+f"(acc[2 * tp][0]), "+f"(acc[2 * tp][1]),
                       "+f"(acc[2 * tp][2]), "+f"(acc[2 * tp][3])
                     : "r"(a0), "r"(a1), "r"(a2), "r"(a3), "r"(b0), "r"(b1));
        asm volatile("mma.sync.aligned.m16n8k16.row.col.f32.f16.f16.f32 "
                     "{%0,%1,%2,%3}, {%4,%5,%6,%7}, {%8,%9}, {%0,%1,%2,%3};"
                     : "+f"(acc[2 * tp + 1][0]), "+f"(acc[2 * tp + 1][1]),
                       "+f"(acc[2 * tp + 1][2]), "+f"(acc[2 * tp + 1][3])
                     : "r"(a0), "r"(a1), "r"(a2), "r"(a3), "r"(b2), "r"(b3));
      }
    }
    __syncthreads();
  }
#pragma unroll
  for (int nt = 0; nt < 8; nt++) {
    int c0 = warp_n * 64 + nt * 8 + (lane & 3) * 2;
    int r0 = warp_m * 16 + (lane >> 2);
    __half2 lo = __floats2half2_rn(acc[nt][0], acc[nt][1]);
    __half2 hi = __floats2half2_rn(acc[nt][2], acc[nt][3]);
    *(__half2*)&Hs[r0 * HS_STRIDE + c0] = lo;
    *(__half2*)&Hs[(r0 + 8) * HS_STRIDE + c0] = hi;
  }
  __syncthreads();
  float4 av = *(const float4*)&a_s[lane * 4];
  float4 dv = *(const float4*)&a_d[lane * 4];
#pragma unroll
  for (int j = 0; j < 8; j++) {
    int n = wid * 8 + j;
    int nd = node0 + n;
    uint2 u = *(uint2*)&Hs[n * HS_STRIDE + lane * 4];
    float2 f0 = __half22float2(*(const __half2*)&u.x);
    float2 f1 = __half22float2(*(const __half2*)&u.y);
    if (nd < NN) *(uint2*)&g_h1h[(long long)nd * 128 + lane * 4] = u;
    float ps = f0.x * av.x + f0.y * av.y + f1.x * av.z + f1.y * av.w;
    float pd = f0.x * dv.x + f0.y * dv.y + f1.x * dv.z + f1.y * dv.w;
#pragma unroll
    for (int o = 4; o > 0; o >>= 1) {
      ps += __shfl_xor_sync(0xffffffffu, ps, o);
      pd += __shfl_xor_sync(0xffffffffu, pd, o);
    }
    if ((lane & 7) == 0 && nd < NN) {
      g_as1[nd * 4 + (lane >> 3)] = ps;
      g_ad1[nd * 4 + (lane >> 3)] = pd;
    }
  }
}

// ---------------- layer1 fused softmax+aggregate (R8 version: x4 fp32 unroll) ----------------
__global__ __launch_bounds__(256) void k_agg1(const float* __restrict__ b1) {
  __shared__ int   sm_s[8][32];
  __shared__ float sm_e[8][4][32];
  int wip = threadIdx.x >> 5;
  int node = (blockIdx.x * blockDim.x + threadIdx.x) >> 5;
  int lane = threadIdx.x & 31;
  if (node >= NN) return;
  int beg = g_rowptr[node], end = g_rowptr[node + 1];
  float4 adv = *(const float4*)&g_ad1[node * 4];
  int head = lane >> 3;
  float acc0 = 0, acc1 = 0, acc2 = 0, acc3 = 0, den = 0;
  for (int base = beg; base < end; base += 32) {
    int i = base + lane;
    if (i < end) {
      int s = g_srcidx[i];
      float4 asv = *(const float4*)&g_as1[s * 4];
      float t0 = asv.x + adv.x; t0 = t0 > 0.f ? t0 : 0.2f * t0;
      float t1 = asv.y + adv.y; t1 = t1 > 0.f ? t1 : 0.2f * t1;
      float t2 = asv.z + adv.z; t2 = t2 > 0.f ? t2 : 0.2f * t2;
      float t3 = asv.w + adv.w; t3 = t3 > 0.f ? t3 : 0.2f * t3;
      sm_s[wip][lane] = s;
      sm_e[wip][0][lane] = __expf(t0);
      sm_e[wip][1][lane] = __expf(t1);
      sm_e[wip][2][lane] = __expf(t2);
      sm_e[wip][3][lane] = __expf(t3);
    }
    __syncwarp();
    int cnt = min(32, end - base);
    int k = 0;
    for (; k + 4 <= cnt; k += 4) {
      int4   ss = *(const int4*)&sm_s[wip][k];
      float4 ww = *(const float4*)&sm_e[wip][head][k];
      uint2 u0 = *((const uint2*)(g_h1h + (long long)ss.x * 128) + lane);
      uint2 u1 = *((const uint2*)(g_h1h + (long long)ss.y * 128) + lane);
      uint2 u2 = *((const uint2*)(g_h1h + (long long)ss.z * 128) + lane);
      uint2 u3 = *((const uint2*)(g_h1h + (long long)ss.w * 128) + lane);
      float2 a0 = __half22float2(*(const __half2*)&u0.x);
      float2 b0 = __half22float2(*(const __half2*)&u0.y);
      float2 a1 = __half22float2(*(const __half2*)&u1.x);
      float2 b1v = __half22float2(*(const __half2*)&u1.y);
      float2 a2 = __half22float2(*(const __half2*)&u2.x);
      float2 b2v = __half22float2(*(const __half2*)&u2.y);
      float2 a3 = __half22float2(*(const __half2*)&u3.x);
      float2 b3v = __half22float2(*(const __half2*)&u3.y);
      acc0 = fmaf(ww.x, a0.x, acc0); acc1 = fmaf(ww.x, a0.y, acc1);
      acc2 = fmaf(ww.x, b0.x, acc2); acc3 = fmaf(ww.x, b0.y, acc3);
      acc0 = fmaf(ww.y, a1.x, acc0); acc1 = fmaf(ww.y, a1.y, acc1);
      acc2 = fmaf(ww.y, b1v.x, acc2); acc3 = fmaf(ww.y, b1v.y, acc3);
      acc0 = fmaf(ww.z, a2.x, acc0); acc1 = fmaf(ww.z, a2.y, acc1);
      acc2 = fmaf(ww.z, b2v.x, acc2); acc3 = fmaf(ww.z, b2v.y, acc3);
      acc0 = fmaf(ww.w, a3.x, acc0); acc1 = fmaf(ww.w, a3.y, acc1);
      acc2 = fmaf(ww.w, b3v.x, acc2); acc3 = fmaf(ww.w, b3v.y, acc3);
      den += (ww.x + ww.y) + (ww.z + ww.w);
    }
    for (; k < cnt; k++) {
      int s = sm_s[wip][k];
      float w = sm_e[wip][head][k];
      uint2 u = *((const uint2*)(g_h1h + (long long)s * 128) + lane);
      float2 f0 = __half22float2(*(const __half2*)&u.x);
      float2 f1 = __half22float2(*(const __half2*)&u.y);
      acc0 = fmaf(w, f0.x, acc0);
      acc1 = fmaf(w, f0.y, acc1);
      acc2 = fmaf(w, f1.x, acc2);
      acc3 = fmaf(w, f1.y, acc3);
      den += w;
    }
    __syncwarp();
  }
  float inv = 1.0f / den;
  int c0 = lane * 4;
  float v0 = acc0 * inv + b1[c0];
  float v1 = acc1 * inv + b1[c0 + 1];
  float v2 = acc2 * inv + b1[c0 + 2];
  float v3 = acc3 * inv + b1[c0 + 3];
  v0 = v0 > 0.f ? v0 : expm1f(v0);
  v1 = v1 > 0.f ? v1 : expm1f(v1);
  v2 = v2 > 0.f ? v2 : expm1f(v2);
  v3 = v3 > 0.f ? v3 : expm1f(v3);
  __half2 h0 = __floats2half2_rn(v0, v1);
  __half2 h1 = __floats2half2_rn(v2, v3);
  uint2 st;
  st.x = *(unsigned int*)&h0;
  st.y = *(unsigned int*)&h1;
  *((uint2*)(g_x2h + (long long)node * 128) + lane) = st;
}

// ---------------- layer2 linear ----------------
__global__ __launch_bounds__(256) void k_gemm2(
    const float* __restrict__ W2, const float* __restrict__ a_s,
    const float* __restrict__ a_d) {
  __shared__ float xsT2[128][36];
  int t = threadIdx.x;
  int node0 = blockIdx.x * 32;
  for (int i = t; i < 32 * 64; i += 256) {
    int m = i >> 6, k2 = i & 63;
    int nd = node0 + m;
    float2 f = (nd < NN)
        ? __half22float2(*((const __half2*)(g_x2h + (long long)nd * 128) + k2))
        : make_float2(0.f, 0.f);
    xsT2[2 * k2][m] = f.x;
    xsT2[2 * k2 + 1][m] = f.y;
  }
  __syncthreads();
  int c = t & 31;
  int g = t >> 5;
  float acc[4] = {0.f, 0.f, 0.f, 0.f};
#pragma unroll 8
  for (int k = 0; k < 128; k++) {
    float w = W2[k * 32 + c];
    float4 xv = *(const float4*)&xsT2[k][4 * g];
    acc[0] = fmaf(xv.x, w, acc[0]);
    acc[1] = fmaf(xv.y, w, acc[1]);
    acc[2] = fmaf(xv.z, w, acc[2]);
    acc[3] = fmaf(xv.w, w, acc[3]);
  }
  float asv = a_s[c], adv = a_d[c];
#pragma unroll
  for (int j = 0; j < 4; j++) {
    int nd = node0 + 4 * g + j;
    if (nd >= NN) continue;
    g_h2h[nd * 32 + c] = __float2half_rn(acc[j]);
    float ps = acc[j] * asv;
    float pd = acc[j] * adv;
#pragma unroll
    for (int o = 16; o > 0; o >>= 1) {
      ps += __shfl_xor_sync(0xffffffffu, ps, o);
      pd += __shfl_xor_sync(0xffffffffu, pd, o);
    }
    if (c == 0) { g_as2[nd] = ps; g_ad2[nd] = pd; }
  }
}

// ---------------- layer2 fused softmax+aggregate + pool (R8 version) ----------------
__global__ __launch_bounds__(256) void k_agg2(const float* __restrict__ b2,
                                              const void* batch) {
  __shared__ int   sm_s[8][32];
  __shared__ float sm_e[8][32];
  int wip = threadIdx.x >> 5;
  int node = (blockIdx.x * blockDim.x + threadIdx.x) >> 5;
  int lane = threadIdx.x & 31;
  if (node >= NN) return;
  int beg = g_rowptr[node], end = g_rowptr[node + 1];
  float adv = g_ad2[node];
  float acc = 0.f, den = 0.f;
  for (int base = beg; base < end; base += 32) {
    int i = base + lane;
    if (i < end) {
      int s = g_srcidx[i];
      float a = g_as2[s] + adv;
      a = a > 0.f ? a : 0.2f * a;
      sm_s[wip][lane] = s;
      sm_e[wip][lane] = __expf(a);
    }
    __syncwarp();
    int cnt = min(32, end - base);
    int k = 0;
    for (; k + 4 <= cnt; k += 4) {
      int4   ss = *(const int4*)&sm_s[wip][k];
      float4 ww = *(const float4*)&sm_e[wip][k];
      __half h0 = g_h2h[ss.x * 32 + lane];
      __half h1 = g_h2h[ss.y * 32 + lane];
      __half h2 = g_h2h[ss.z * 32 + lane];
      __half h3 = g_h2h[ss.w * 32 + lane];
      acc = fmaf(ww.x, __half2float(h0), acc);
      acc = fmaf(ww.y, __half2float(h1), acc);
      acc = fmaf(ww.z, __half2float(h2), acc);
      acc = fmaf(ww.w, __half2float(h3), acc);
      den += (ww.x + ww.y) + (ww.z + ww.w);
    }
    for (; k < cnt; k++) {
      float w = sm_e[wip][k];
      acc = fmaf(w, __half2float(g_h2h[sm_s[wip][k] * 32 + lane]), acc);
      den += w;
    }
    __syncwarp();
  }
  float v = acc / den + b2[lane];
  v = v > 0.f ? v : expm1f(v);
  int gph = idx_at(batch, g_is64, node);
  atomicAdd(&g_pooled[gph * 32 + lane], v);
}

// ---------------- classifier + state reset ----------------
__global__ void k_cls(const float* __restrict__ Wc1, const float* __restrict__ bc1,
                      const float* __restrict__ Wc2, const float* __restrict__ bc2,
                      float* __restrict__ out) {
  int i = blockIdx.x * blockDim.x + threadIdx.x;
  if (i < NN) g_deg[i] = 0;
  if (i >= GG) return;
  int g = i;
  float inv = 1.0f / g_cnt[g];
  float p[32];
#pragma unroll
  for (int c = 0; c < 32; c++) {
    p[c] = g_pooled[g * 32 + c] * inv;
    g_pooled[g * 32 + c] = 0.f;
  }
  g_cnt[g] = 0.f;
  float o = bc2[0];
#pragma unroll
  for (int j = 0; j < 16; j++) {
    float z = bc1[j];
#pragma unroll
    for (int c = 0; c < 32; c++) z = fmaf(p[c], Wc1[c * 16 + j], z);
    if (z > 0.f) o = fmaf(z, Wc2[j], o);
  }
  out[g] = o;
}

// ---------------- launch ----------------
extern "C" void kernel_launch(void* const* d_in, const int* in_sizes, int n_in,
                              void* d_out, int out_size) {
  const float* x   = (const float*)d_in[0];
  const void*  ei  = d_in[1];
  const void*  bat = d_in[3];
  const float* W1  = (const float*)d_in[4];
  const float* as1 = (const float*)d_in[5];
  const float* ad1 = (const float*)d_in[6];
  const float* b1  = (const float*)d_in[7];
  const float* W2  = (const float*)d_in[8];
  const float* as2 = (const float*)d_in[9];
  const float* ad2 = (const float*)d_in[10];
  const float* b2  = (const float*)d_in[11];
  const float* Wc1 = (const float*)d_in[12];
  const float* bc1 = (const float*)d_in[13];
  const float* Wc2 = (const float*)d_in[14];
  const float* bc2 = (const float*)d_in[15];
  float* out = (float*)d_out;

  k_count<<<(HE + NN + 255) / 256 + CVTB, 256>>>(ei, bat, W1);
  k_blockscan<<<NB, 256>>>();
  k_rowptr<<<NB, 256>>>();
  k_gs<<<GB1 + SCB, 256>>>(x, as1, ad1, ei);       // 4th launch -> ncu window
  k_agg1<<<(NN * 32 + 255) / 256, 256>>>(b1);
  k_gemm2<<<(NN + 31) / 32, 256>>>(W2, as2, ad2);
  k_agg2<<<(NN * 32 + 255) / 256, 256>>>(b2, bat);
  k_cls<<<NB, 256>>>(Wc1, bc1, Wc2, bc2, out);
}

// round 11
// speedup vs baseline: 1.0804x; 1.0229x over previous
#include <cuda_runtime.h>
#include <cuda_fp16.h>

#define NN 50000
#define EE 1600000
#define GG 512
#define ETOT (EE + NN)
#define NB ((NN + 255) / 256)
#define HE (EE / 2)
#define GB1 ((NN + 63) / 64)
#define SCB ((HE + NN + 255) / 256)
#define CVTB 16

// ---------------- scratch ----------------
__device__ __align__(16) __half g_W1h[128 * 128];
__device__ __align__(16) __half g_h1h[NN * 128];
__device__ float g_as1[NN * 4];
__device__ float g_ad1[NN * 4];
__device__ __align__(16) __half g_x2h[NN * 128];
__device__ __align__(16) __half g_h2h[NN * 32];
__device__ float g_as2[NN];
__device__ float g_ad2[NN];
__device__ int   g_deg[NN];          // starts 0; k_cls re-zeroes
__device__ int   g_rowptr[NN + 1];
__device__ int   g_pos[NN];
__device__ int   g_srcidx[ETOT];
__device__ int   g_boff[NB];
__device__ int   g_arrive;           // self-resets in k_blockscan
__device__ float g_pooled[GG * 32];
__device__ float g_cnt[GG];
__device__ int   g_is64;

__device__ __forceinline__ int idx_at(const void* p, int is64, long long i) {
  return is64 ? (int)((const long long*)p)[i] : ((const int*)p)[i];
}

// ---------------- count: dtype detect + degrees + self-loops + graph counts + cvtW ----------------
__global__ void k_count(const void* ei, const void* batch, const float* __restrict__ W1) {
  __shared__ int s64;
  if (threadIdx.x == 0) {
    const long long* p = (const long long*)ei;
    int ok = 1;
#pragma unroll
    for (int j = 0; j < 8; j++) {
      long long v = p[j];
      if (v < 0 || v >= NN) ok = 0;
    }
    s64 = ok;
    if (blockIdx.x == 0) g_is64 = ok;
  }
  __syncthreads();
  int is64 = s64;
  int i = blockIdx.x * blockDim.x + threadIdx.x;
  if (i < HE) {
    int d0, d1;
    if (is64) {
      longlong2 v = ((const longlong2*)((const long long*)ei + EE))[i];
      d0 = (int)v.x; d1 = (int)v.y;
    } else {
      int2 v = ((const int2*)((const int*)ei + EE))[i];
      d0 = v.x; d1 = v.y;
    }
    atomicAdd(&g_deg[d0], 1);
    atomicAdd(&g_deg[d1], 1);
  } else if (i < HE + NN) {
    int node = i - HE;
    atomicAdd(&g_deg[node], 1);
    atomicAdd(&g_cnt[idx_at(batch, is64, node)], 1.0f);
  } else {
    int j = i - (HE + NN);
    if (j < 128 * 128 / 4) {
      float4 v = ((const float4*)W1)[j];
      __half2 h0 = __floats2half2_rn(v.x, v.y);
      __half2 h1 = __floats2half2_rn(v.z, v.w);
      uint2 u;
      u.x = *(unsigned int*)&h0;
      u.y = *(unsigned int*)&h1;
      ((uint2*)g_W1h)[j] = u;
    }
  }
}

// ---------------- block sums + last-block exclusive scan ----------------
__global__ void k_blockscan() {
  __shared__ int ws[8];
  __shared__ int sm[256];
  __shared__ int isLast;
  int t = threadIdx.x, b = blockIdx.x;
  int i = b * 256 + t;
  int v = (i < NN) ? g_deg[i] : 0;
#pragma unroll
  for (int o = 16; o; o >>= 1) v += __shfl_down_sync(0xffffffffu, v, o);
  if ((t & 31) == 0) ws[t >> 5] = v;
  __syncthreads();
  if (t == 0) {
    int s = 0;
#pragma unroll
    for (int j = 0; j < 8; j++) s += ws[j];
    g_boff[b] = s;
    __threadfence();
    int old = atomicAdd(&g_arrive, 1);
    isLast = (old == NB - 1);
  }
  __syncthreads();
  if (!isLast) return;
  int vv = (t < NB) ? g_boff[t] : 0;
  sm[t] = vv;
  __syncthreads();
  for (int o = 1; o < 256; o <<= 1) {
    int u = (t >= o) ? sm[t - o] : 0;
    __syncthreads();
    sm[t] += u;
    __syncthreads();
  }
  if (t < NB) g_boff[t] = sm[t] - vv;
  if (t == 255) g_rowptr[NN] = sm[255];
  if (t == 0) g_arrive = 0;
}

__global__ void k_rowptr() {
  int t = threadIdx.x, b = blockIdx.x;
  int i = b * 256 + t;
  int v = (i < NN) ? g_deg[i] : 0;
  int lane = t & 31, w = t >> 5;
  int x = v;
#pragma unroll
  for (int o = 1; o < 32; o <<= 1) {
    int u = __shfl_up_sync(0xffffffffu, x, o);
    if (lane >= o) x += u;
  }
  __shared__ int ws[8], wo[8];
  if (lane == 31) ws[w] = x;
  __syncthreads();
  if (t == 0) {
    int r = 0;
#pragma unroll
    for (int j = 0; j < 8; j++) { wo[j] = r; r += ws[j]; }
  }
  __syncthreads();
  int off = g_boff[b] + wo[w] + x - v;
  if (i < NN) { g_rowptr[i] = off; g_pos[i] = off; }
}

// ---------------- FUSED: gemm1 (blocks < GB1) + scatter (blocks >= GB1) ----------------
#define AS_STRIDE 40
#define BS_STRIDE 136
#define HS_STRIDE 132
#define AS_BYTES (64 * AS_STRIDE * 2)                 // 5120
#define ABS_BYTES (AS_BYTES + 32 * BS_STRIDE * 2)     // 13824
#define HS_BYTES (64 * HS_STRIDE * 2)                 // 16896
#define SM_BYTES (HS_BYTES > ABS_BYTES ? HS_BYTES : ABS_BYTES)

__global__ __launch_bounds__(256) void k_gs(
    const float* __restrict__ x,
    const float* __restrict__ a_s, const float* __restrict__ a_d,
    const void* ei) {
  // Hs aliases As+Bs: Hs is only touched after the mainloop's final
  // __syncthreads (all mma reads of As/Bs complete by then).
  __shared__ __align__(16) char smem_raw[SM_BYTES];
  __half* As = (__half*)smem_raw;
  __half* Bs = (__half*)(smem_raw + AS_BYTES);
  __half* Hs = (__half*)smem_raw;

  if (blockIdx.x >= GB1) {
    // ----- scatter path (latency-bound; overlaps with gemm blocks) -----
    int i = (blockIdx.x - GB1) * 256 + threadIdx.x;
    int is64 = g_is64;
    if (i < HE) {
      int s0, s1, d0, d1;
      if (is64) {
        const long long* p = (const long long*)ei;
        longlong2 sv = ((const longlong2*)p)[i];
        longlong2 dv = ((const longlong2*)(p + EE))[i];
        s0 = (int)sv.x; s1 = (int)sv.y; d0 = (int)dv.x; d1 = (int)dv.y;
      } else {
        const int* p = (const int*)ei;
        int2 sv = ((const int2*)p)[i];
        int2 dv = ((const int2*)(p + EE))[i];
        s0 = sv.x; s1 = sv.y; d0 = dv.x; d1 = dv.y;
      }
      g_srcidx[atomicAdd(&g_pos[d0], 1)] = s0;
      g_srcidx[atomicAdd(&g_pos[d1], 1)] = s1;
    } else {
      int node = i - HE;
      if (node < NN) g_srcidx[atomicAdd(&g_pos[node], 1)] = node;
    }
    return;
  }

  // ----- gemm1 path (mma.sync) -----
  int t = threadIdx.x;
  int lane = t & 31, wid = t >> 5;
  int warp_m = wid >> 1;
  int warp_n = wid & 1;
  int node0 = blockIdx.x * 64;

  float acc[8][4];
#pragma unroll
  for (int nt = 0; nt < 8; nt++)
#pragma unroll
    for (int j = 0; j < 4; j++) acc[nt][j] = 0.f;

  for (int c = 0; c < 4; c++) {
    int k0 = c * 32;
#pragma unroll
    for (int r = 0; r < 2; r++) {
      int i = t * 2 + r;
      int nd = i >> 3, kj = (i & 7) * 4;
      float4 v = (node0 + nd < NN)
          ? *(const float4*)&x[(long long)(node0 + nd) * 128 + k0 + kj]
          : make_float4(0.f, 0.f, 0.f, 0.f);
      __half2 h0 = __floats2half2_rn(v.x, v.y);
      __half2 h1 = __floats2half2_rn(v.z, v.w);
      uint2 u;
      u.x = *(unsigned int*)&h0;
      u.y = *(unsigned int*)&h1;
      *(uint2*)&As[nd * AS_STRIDE + kj] = u;
    }
#pragma unroll
    for (int r = 0; r < 4; r++) {
      int i = t * 4 + r;
      int kr = i >> 5, c4 = (i & 31) * 4;
      uint2 u = *(const uint2*)&g_W1h[(k0 + kr) * 128 + c4];
      *(uint2*)&Bs[kr * BS_STRIDE + c4] = u;
    }
    __syncthreads();
#pragma unroll
    for (int kk = 0; kk < 32; kk += 16) {
      unsigned int a0, a1, a2, a3;
      {
        unsigned int addr = (unsigned int)__cvta_generic_to_shared(
            &As[(warp_m * 16 + (lane & 15)) * AS_STRIDE + kk + ((lane >> 4) << 3)]);
        asm volatile("ldmatrix.sync.aligned.m8n8.x4.shared.b16 {%0,%1,%2,%3}, [%4];"
                     : "=r"(a0), "=r"(a1), "=r"(a2), "=r"(a3) : "r"(addr));
      }
#pragma unroll
      for (int tp = 0; tp < 4; tp++) {
        unsigned int b0, b1, b2, b3;
        unsigned int addr = (unsigned int)__cvta_generic_to_shared(
            &Bs[(kk + (lane & 15)) * BS_STRIDE + warp_n * 64 + tp * 16 + ((lane >> 4) << 3)]);
        asm volatile("ldmatrix.sync.aligned.m8n8.x4.trans.shared.b16 {%0,%1,%2,%3}, [%4];"
                     : "=r"(b0), "=r"(b1), "=r"(b2), "=r"(b3) : "r"(addr));
        asm volatile("mma.sync.aligned.m16n8k16.row.col.f32.f16.f16.f32 "
                     "{%0,%1,%2,%3}, {%4,%5,%6,%7}, {%8,%9}, {%0,%1,%2,%3};"
                     : "+f"(acc[2 * tp][0]), "+f"(acc[2 * tp][1]),
                       "+f"(acc[2 * tp][2]), "+f"(acc[2 * tp][3])
                     : "r"(a0), "r"(a1), "r"(a2), "r"(a3), "r"(b0), "r"(b1));
        asm volatile("mma.sync.aligned.m16n8k16.row.col.f32.f16.f16.f32 "
                     "{%0,%1,%2,%3}, {%4,%5,%6,%7}, {%8,%9}, {%0,%1,%2,%3};"
                     : "+f"(acc[2 * tp + 1][0]), "+f"(acc[2 * tp + 1][1]),
                       "+f"(acc[2 * tp + 1][2]), "+f"(acc[2 * tp + 1][3])
                     : "r"(a0), "r"(a1), "r"(a2), "r"(a3), "r"(b2), "r"(b3));
      }
    }
    __syncthreads();
  }
  // accums -> Hs (aliases As/Bs; safe after the final mainloop sync above)
#pragma unroll
  for (int nt = 0; nt < 8; nt++) {
    int c0 = warp_n * 64 + nt * 8 + (lane & 3) * 2;
    int r0 = warp_m * 16 + (lane >> 2);
    __half2 lo = __floats2half2_rn(acc[nt][0], acc[nt][1]);
    __half2 hi = __floats2half2_rn(acc[nt][2], acc[nt][3]);
    *(__half2*)&Hs[r0 * HS_STRIDE + c0] = lo;
    *(__half2*)&Hs[(r0 + 8) * HS_STRIDE + c0] = hi;
  }
  __syncthreads();
  float4 av = *(const float4*)&a_s[lane * 4];
  float4 dv = *(const float4*)&a_d[lane * 4];
#pragma unroll
  for (int j = 0; j < 8; j++) {
    int n = wid * 8 + j;
    int nd = node0 + n;
    uint2 u = *(uint2*)&Hs[n * HS_STRIDE + lane * 4];
    float2 f0 = __half22float2(*(const __half2*)&u.x);
    float2 f1 = __half22float2(*(const __half2*)&u.y);
    if (nd < NN) *(uint2*)&g_h1h[(long long)nd * 128 + lane * 4] = u;
    float ps = f0.x * av.x + f0.y * av.y + f1.x * av.z + f1.y * av.w;
    float pd = f0.x * dv.x + f0.y * dv.y + f1.x * dv.z + f1.y * dv.w;
#pragma unroll
    for (int o = 4; o > 0; o >>= 1) {
      ps += __shfl_xor_sync(0xffffffffu, ps, o);
      pd += __shfl_xor_sync(0xffffffffu, pd, o);
    }
    if ((lane & 7) == 0 && nd < NN) {
      g_as1[nd * 4 + (lane >> 3)] = ps;
      g_ad1[nd * 4 + (lane >> 3)] = pd;
    }
  }
}

// ---------------- layer1 fused softmax+aggregate (64-thr blocks: less retire imbalance) ----------------
__global__ __launch_bounds__(64) void k_agg1(const float* __restrict__ b1) {
  __shared__ int   sm_s[2][32];
  __shared__ float sm_e[2][4][32];
  int wip = threadIdx.x >> 5;
  int node = blockIdx.x * 2 + wip;
  int lane = threadIdx.x & 31;
  if (node >= NN) return;
  int beg = g_rowptr[node], end = g_rowptr[node + 1];
  float4 adv = *(const float4*)&g_ad1[node * 4];
  int head = lane >> 3;
  float acc0 = 0, acc1 = 0, acc2 = 0, acc3 = 0, den = 0;
  for (int base = beg; base < end; base += 32) {
    int i = base + lane;
    if (i < end) {
      int s = g_srcidx[i];
      float4 asv = *(const float4*)&g_as1[s * 4];
      float t0 = asv.x + adv.x; t0 = t0 > 0.f ? t0 : 0.2f * t0;
      float t1 = asv.y + adv.y; t1 = t1 > 0.f ? t1 : 0.2f * t1;
      float t2 = asv.z + adv.z; t2 = t2 > 0.f ? t2 : 0.2f * t2;
      float t3 = asv.w + adv.w; t3 = t3 > 0.f ? t3 : 0.2f * t3;
      sm_s[wip][lane] = s;
      sm_e[wip][0][lane] = __expf(t0);
      sm_e[wip][1][lane] = __expf(t1);
      sm_e[wip][2][lane] = __expf(t2);
      sm_e[wip][3][lane] = __expf(t3);
    }
    __syncwarp();
    int cnt = min(32, end - base);
    int k = 0;
    for (; k + 4 <= cnt; k += 4) {
      int4   ss = *(const int4*)&sm_s[wip][k];
      float4 ww = *(const float4*)&sm_e[wip][head][k];
      uint2 u0 = *((const uint2*)(g_h1h + (long long)ss.x * 128) + lane);
      uint2 u1 = *((const uint2*)(g_h1h + (long long)ss.y * 128) + lane);
      uint2 u2 = *((const uint2*)(g_h1h + (long long)ss.z * 128) + lane);
      uint2 u3 = *((const uint2*)(g_h1h + (long long)ss.w * 128) + lane);
      float2 a0 = __half22float2(*(const __half2*)&u0.x);
      float2 b0 = __half22float2(*(const __half2*)&u0.y);
      float2 a1 = __half22float2(*(const __half2*)&u1.x);
      float2 b1v = __half22float2(*(const __half2*)&u1.y);
      float2 a2 = __half22float2(*(const __half2*)&u2.x);
      float2 b2v = __half22float2(*(const __half2*)&u2.y);
      float2 a3 = __half22float2(*(const __half2*)&u3.x);
      float2 b3v = __half22float2(*(const __half2*)&u3.y);
      acc0 = fmaf(ww.x, a0.x, acc0); acc1 = fmaf(ww.x, a0.y, acc1);
      acc2 = fmaf(ww.x, b0.x, acc2); acc3 = fmaf(ww.x, b0.y, acc3);
      acc0 = fmaf(ww.y, a1.x, acc0); acc1 = fmaf(ww.y, a1.y, acc1);
      acc2 = fmaf(ww.y, b1v.x, acc2); acc3 = fmaf(ww.y, b1v.y, acc3);
      acc0 = fmaf(ww.z, a2.x, acc0); acc1 = fmaf(ww.z, a2.y, acc1);
      acc2 = fmaf(ww.z, b2v.x, acc2); acc3 = fmaf(ww.z, b2v.y, acc3);
      acc0 = fmaf(ww.w, a3.x, acc0); acc1 = fmaf(ww.w, a3.y, acc1);
      acc2 = fmaf(ww.w, b3v.x, acc2); acc3 = fmaf(ww.w, b3v.y, acc3);
      den += (ww.x + ww.y) + (ww.z + ww.w);
    }
    for (; k < cnt; k++) {
      int s = sm_s[wip][k];
      float w = sm_e[wip][head][k];
      uint2 u = *((const uint2*)(g_h1h + (long long)s * 128) + lane);
      float2 f0 = __half22float2(*(const __half2*)&u.x);
      float2 f1 = __half22float2(*(const __half2*)&u.y);
      acc0 = fmaf(w, f0.x, acc0);
      acc1 = fmaf(w, f0.y, acc1);
      acc2 = fmaf(w, f1.x, acc2);
      acc3 = fmaf(w, f1.y, acc3);
      den += w;
    }
    __syncwarp();
  }
  float inv = 1.0f / den;
  int c0 = lane * 4;
  float v0 = acc0 * inv + b1[c0];
  float v1 = acc1 * inv + b1[c0 + 1];
  float v2 = acc2 * inv + b1[c0 + 2];
  float v3 = acc3 * inv + b1[c0 + 3];
  v0 = v0 > 0.f ? v0 : expm1f(v0);
  v1 = v1 > 0.f ? v1 : expm1f(v1);
  v2 = v2 > 0.f ? v2 : expm1f(v2);
  v3 = v3 > 0.f ? v3 : expm1f(v3);
  __half2 h0 = __floats2half2_rn(v0, v1);
  __half2 h1 = __floats2half2_rn(v2, v3);
  uint2 st;
  st.x = *(unsigned int*)&h0;
  st.y = *(unsigned int*)&h1;
  *((uint2*)(g_x2h + (long long)node * 128) + lane) = st;
}

// ---------------- layer2 linear ----------------
__global__ __launch_bounds__(256) void k_gemm2(
    const float* __restrict__ W2, const float* __restrict__ a_s,
    const float* __restrict__ a_d) {
  __shared__ float xsT2[128][36];
  int t = threadIdx.x;
  int node0 = blockIdx.x * 32;
  for (int i = t; i < 32 * 64; i += 256) {
    int m = i >> 6, k2 = i & 63;
    int nd = node0 + m;
    float2 f = (nd < NN)
        ? __half22float2(*((const __half2*)(g_x2h + (long long)nd * 128) + k2))
        : make_float2(0.f, 0.f);
    xsT2[2 * k2][m] = f.x;
    xsT2[2 * k2 + 1][m] = f.y;
  }
  __syncthreads();
  int c = t & 31;
  int g = t >> 5;
  float acc[4] = {0.f, 0.f, 0.f, 0.f};
#pragma unroll 8
  for (int k = 0; k < 128; k++) {
    float w = W2[k * 32 + c];
    float4 xv = *(const float4*)&xsT2[k][4 * g];
    acc[0] = fmaf(xv.x, w, acc[0]);
    acc[1] = fmaf(xv.y, w, acc[1]);
    acc[2] = fmaf(xv.z, w, acc[2]);
    acc[3] = fmaf(xv.w, w, acc[3]);
  }
  float asv = a_s[c], adv = a_d[c];
#pragma unroll
  for (int j = 0; j < 4; j++) {
    int nd = node0 + 4 * g + j;
    if (nd >= NN) continue;
    g_h2h[nd * 32 + c] = __float2half_rn(acc[j]);
    float ps = acc[j] * asv;
    float pd = acc[j] * adv;
#pragma unroll
    for (int o = 16; o > 0; o >>= 1) {
      ps += __shfl_xor_sync(0xffffffffu, ps, o);
      pd += __shfl_xor_sync(0xffffffffu, pd, o);
    }
    if (c == 0) { g_as2[nd] = ps; g_ad2[nd] = pd; }
  }
}

// ---------------- layer2 fused softmax+aggregate + pool (64-thr blocks) ----------------
__global__ __launch_bounds__(64) void k_agg2(const float* __restrict__ b2,
                                             const void* batch) {
  __shared__ int   sm_s[2][32];
  __shared__ float sm_e[2][32];
  int wip = threadIdx.x >> 5;
  int node = blockIdx.x * 2 + wip;
  int lane = threadIdx.x & 31;
  if (node >= NN) return;
  int beg = g_rowptr[node], end = g_rowptr[node + 1];
  float adv = g_ad2[node];
  float acc = 0.f, den = 0.f;
  for (int base = beg; base < end; base += 32) {
    int i = base + lane;
    if (i < end) {
      int s = g_srcidx[i];
      float a = g_as2[s] + adv;
      a = a > 0.f ? a : 0.2f * a;
      sm_s[wip][lane] = s;
      sm_e[wip][lane] = __expf(a);
    }
    __syncwarp();
    int cnt = min(32, end - base);
    int k = 0;
    for (; k + 4 <= cnt; k += 4) {
      int4   ss = *(const int4*)&sm_s[wip][k];
      float4 ww = *(const float4*)&sm_e[wip][k];
      __half h0 = g_h2h[ss.x * 32 + lane];
      __half h1 = g_h2h[ss.y * 32 + lane];
      __half h2 = g_h2h[ss.z * 32 + lane];
      __half h3 = g_h2h[ss.w * 32 + lane];
      acc = fmaf(ww.x, __half2float(h0), acc);
      acc = fmaf(ww.y, __half2float(h1), acc);
      acc = fmaf(ww.z, __half2float(h2), acc);
      acc = fmaf(ww.w, __half2float(h3), acc);
      den += (ww.x + ww.y) + (ww.z + ww.w);
    }
    for (; k < cnt; k++) {
      float w = sm_e[wip][k];
      acc = fmaf(w, __half2float(g_h2h[sm_s[wip][k] * 32 + lane]), acc);
      den += w;
    }
    __syncwarp();
  }
  float v = acc / den + b2[lane];
  v = v > 0.f ? v : expm1f(v);
  int gph = idx_at(batch, g_is64, node);
  atomicAdd(&g_pooled[gph * 32 + lane], v);
}

// ---------------- classifier + state reset ----------------
__global__ void k_cls(const float* __restrict__ Wc1, const float* __restrict__ bc1,
                      const float* __restrict__ Wc2, const float* __restrict__ bc2,
                      float* __restrict__ out) {
  int i = blockIdx.x * blockDim.x + threadIdx.x;
  if (i < NN) g_deg[i] = 0;
  if (i >= GG) return;
  int g = i;
  float inv = 1.0f / g_cnt[g];
  float p[32];
#pragma unroll
  for (int c = 0; c < 32; c++) {
    p[c] = g_pooled[g * 32 + c] * inv;
    g_pooled[g * 32 + c] = 0.f;
  }
  g_cnt[g] = 0.f;
  float o = bc2[0];
#pragma unroll
  for (int j = 0; j < 16; j++) {
    float z = bc1[j];
#pragma unroll
    for (int c = 0; c < 32; c++) z = fmaf(p[c], Wc1[c * 16 + j], z);
    if (z > 0.f) o = fmaf(z, Wc2[j], o);
  }
  out[g] = o;
}

// ---------------- launch ----------------
extern "C" void kernel_launch(void* const* d_in, const int* in_sizes, int n_in,
                              void* d_out, int out_size) {
  const float* x   = (const float*)d_in[0];
  const void*  ei  = d_in[1];
  const void*  bat = d_in[3];
  const float* W1  = (const float*)d_in[4];
  const float* as1 = (const float*)d_in[5];
  const float* ad1 = (const float*)d_in[6];
  const float* b1  = (const float*)d_in[7];
  const float* W2  = (const float*)d_in[8];
  const float* as2 = (const float*)d_in[9];
  const float* ad2 = (const float*)d_in[10];
  const float* b2  = (const float*)d_in[11];
  const float* Wc1 = (const float*)d_in[12];
  const float* bc1 = (const float*)d_in[13];
  const float* Wc2 = (const float*)d_in[14];
  const float* bc2 = (const float*)d_in[15];
  float* out = (float*)d_out;

  k_count<<<(HE + NN + 255) / 256 + CVTB, 256>>>(ei, bat, W1);
  k_blockscan<<<NB, 256>>>();
  k_rowptr<<<NB, 256>>>();
  k_gs<<<GB1 + SCB, 256>>>(x, as1, ad1, ei);       // 4th launch -> ncu window
  k_agg1<<<(NN + 1) / 2, 64>>>(b1);
  k_gemm2<<<(NN + 31) / 32, 256>>>(W2, as2, ad2);
  k_agg2<<<(NN + 1) / 2, 64>>>(b2, bat);
  k_cls<<<NB, 256>>>(Wc1, bc1, Wc2, bc2, out);
}

// round 12
// speedup vs baseline: 1.0930x; 1.0116x over previous
#include <cuda_runtime.h>
#include <cuda_fp16.h>

#define NN 50000
#define EE 1600000
#define GG 512
#define ETOT (EE + NN)
#define NB ((NN + 255) / 256)
#define HE (EE / 2)
#define GB1 ((NN + 63) / 64)
#define SCB ((HE + NN + 255) / 256)
#define CVTB 16

// ---------------- scratch ----------------
__device__ __align__(16) __half g_W1h[128 * 128];
__device__ __align__(16) __half g_h1h[NN * 128];
__device__ float g_as1[NN * 4];
__device__ float g_ad1[NN * 4];
__device__ __align__(16) __half g_x2h[NN * 128];
__device__ __align__(16) __half g_h2h[NN * 32];
__device__ float g_as2[NN];
__device__ float g_ad2[NN];
__device__ int   g_deg[NN];          // starts 0; k_cls re-zeroes
__device__ int   g_rowptr[NN + 1];
__device__ int   g_pos[NN];
__device__ int   g_srcidx[ETOT];
__device__ int   g_boff[NB];
__device__ int   g_arrive;           // self-resets in k_blockscan
__device__ float g_pooled[GG * 32];
__device__ float g_cnt[GG];
__device__ int   g_is64;

__device__ __forceinline__ int idx_at(const void* p, int is64, long long i) {
  return is64 ? (int)((const long long*)p)[i] : ((const int*)p)[i];
}

// ---------------- count: dtype detect + degrees + self-loops + graph counts + cvtW ----------------
__global__ void k_count(const void* ei, const void* batch, const float* __restrict__ W1) {
  __shared__ int s64;
  if (threadIdx.x == 0) {
    const long long* p = (const long long*)ei;
    int ok = 1;
#pragma unroll
    for (int j = 0; j < 8; j++) {
      long long v = p[j];
      if (v < 0 || v >= NN) ok = 0;
    }
    s64 = ok;
    if (blockIdx.x == 0) g_is64 = ok;
  }
  __syncthreads();
  int is64 = s64;
  int i = blockIdx.x * blockDim.x + threadIdx.x;
  if (i < HE) {
    int d0, d1;
    if (is64) {
      longlong2 v = ((const longlong2*)((const long long*)ei + EE))[i];
      d0 = (int)v.x; d1 = (int)v.y;
    } else {
      int2 v = ((const int2*)((const int*)ei + EE))[i];
      d0 = v.x; d1 = v.y;
    }
    atomicAdd(&g_deg[d0], 1);
    atomicAdd(&g_deg[d1], 1);
  } else if (i < HE + NN) {
    int node = i - HE;
    atomicAdd(&g_deg[node], 1);
    atomicAdd(&g_cnt[idx_at(batch, is64, node)], 1.0f);
  } else {
    int j = i - (HE + NN);
    if (j < 128 * 128 / 4) {
      float4 v = ((const float4*)W1)[j];
      __half2 h0 = __floats2half2_rn(v.x, v.y);
      __half2 h1 = __floats2half2_rn(v.z, v.w);
      uint2 u;
      u.x = *(unsigned int*)&h0;
      u.y = *(unsigned int*)&h1;
      ((uint2*)g_W1h)[j] = u;
    }
  }
}

// ---------------- block sums + last-block exclusive scan ----------------
__global__ void k_blockscan() {
  __shared__ int ws[8];
  __shared__ int sm[256];
  __shared__ int isLast;
  int t = threadIdx.x, b = blockIdx.x;
  int i = b * 256 + t;
  int v = (i < NN) ? g_deg[i] : 0;
#pragma unroll
  for (int o = 16; o; o >>= 1) v += __shfl_down_sync(0xffffffffu, v, o);
  if ((t & 31) == 0) ws[t >> 5] = v;
  __syncthreads();
  if (t == 0) {
    int s = 0;
#pragma unroll
    for (int j = 0; j < 8; j++) s += ws[j];
    g_boff[b] = s;
    __threadfence();
    int old = atomicAdd(&g_arrive, 1);
    isLast = (old == NB - 1);
  }
  __syncthreads();
  if (!isLast) return;
  int vv = (t < NB) ? g_boff[t] : 0;
  sm[t] = vv;
  __syncthreads();
  for (int o = 1; o < 256; o <<= 1) {
    int u = (t >= o) ? sm[t - o] : 0;
    __syncthreads();
    sm[t] += u;
    __syncthreads();
  }
  if (t < NB) g_boff[t] = sm[t] - vv;
  if (t == 255) g_rowptr[NN] = sm[255];
  if (t == 0) g_arrive = 0;
}

__global__ void k_rowptr() {
  int t = threadIdx.x, b = blockIdx.x;
  int i = b * 256 + t;
  int v = (i < NN) ? g_deg[i] : 0;
  int lane = t & 31, w = t >> 5;
  int x = v;
#pragma unroll
  for (int o = 1; o < 32; o <<= 1) {
    int u = __shfl_up_sync(0xffffffffu, x, o);
    if (lane >= o) x += u;
  }
  __shared__ int ws[8], wo[8];
  if (lane == 31) ws[w] = x;
  __syncthreads();
  if (t == 0) {
    int r = 0;
#pragma unroll
    for (int j = 0; j < 8; j++) { wo[j] = r; r += ws[j]; }
  }
  __syncthreads();
  int off = g_boff[b] + wo[w] + x - v;
  if (i < NN) { g_rowptr[i] = off; g_pos[i] = off; }
}

// ---------------- FUSED: gemm1 + scatter, roles INTERLEAVED (1 gemm per 5 blocks) ----------------
#define AS_STRIDE 40
#define BS_STRIDE 136
#define HS_STRIDE 132
#define AS_BYTES (64 * AS_STRIDE * 2)
#define ABS_BYTES (AS_BYTES + 32 * BS_STRIDE * 2)
#define HS_BYTES (64 * HS_STRIDE * 2)
#define SM_BYTES (HS_BYTES > ABS_BYTES ? HS_BYTES : ABS_BYTES)

__global__ __launch_bounds__(256) void k_gs(
    const float* __restrict__ x,
    const float* __restrict__ a_s, const float* __restrict__ a_d,
    const void* ei) {
  __shared__ __align__(16) char smem_raw[SM_BYTES];
  __half* As = (__half*)smem_raw;
  __half* Bs = (__half*)(smem_raw + AS_BYTES);
  __half* Hs = (__half*)smem_raw;

  int b = blockIdx.x;
  int g = b / 5, r5 = b - g * 5;
  bool isGemm = (r5 == 0) && (g < GB1);

  if (!isGemm) {
    // ----- scatter path: sc = b minus #gemm-blocks-before-b -----
    int sc = b - min((b + 4) / 5, GB1);
    int i = sc * 256 + threadIdx.x;
    int is64 = g_is64;
    if (i < HE) {
      int s0, s1, d0, d1;
      if (is64) {
        const long long* p = (const long long*)ei;
        longlong2 sv = ((const longlong2*)p)[i];
        longlong2 dv = ((const longlong2*)(p + EE))[i];
        s0 = (int)sv.x; s1 = (int)sv.y; d0 = (int)dv.x; d1 = (int)dv.y;
      } else {
        const int* p = (const int*)ei;
        int2 sv = ((const int2*)p)[i];
        int2 dv = ((const int2*)(p + EE))[i];
        s0 = sv.x; s1 = sv.y; d0 = dv.x; d1 = dv.y;
      }
      g_srcidx[atomicAdd(&g_pos[d0], 1)] = s0;
      g_srcidx[atomicAdd(&g_pos[d1], 1)] = s1;
    } else {
      int node = i - HE;
      if (node < NN) g_srcidx[atomicAdd(&g_pos[node], 1)] = node;
    }
    return;
  }

  // ----- gemm1 path (mma.sync); tile index = g -----
  int t = threadIdx.x;
  int lane = t & 31, wid = t >> 5;
  int warp_m = wid >> 1;
  int warp_n = wid & 1;
  int node0 = g * 64;

  float acc[8][4];
#pragma unroll
  for (int nt = 0; nt < 8; nt++)
#pragma unroll
    for (int j = 0; j < 4; j++) acc[nt][j] = 0.f;

  for (int c = 0; c < 4; c++) {
    int k0 = c * 32;
#pragma unroll
    for (int r = 0; r < 2; r++) {
      int i = t * 2 + r;
      int nd = i >> 3, kj = (i & 7) * 4;
      float4 v = (node0 + nd < NN)
          ? *(const float4*)&x[(long long)(node0 + nd) * 128 + k0 + kj]
          : make_float4(0.f, 0.f, 0.f, 0.f);
      __half2 h0 = __floats2half2_rn(v.x, v.y);
      __half2 h1 = __floats2half2_rn(v.z, v.w);
      uint2 u;
      u.x = *(unsigned int*)&h0;
      u.y = *(unsigned int*)&h1;
      *(uint2*)&As[nd * AS_STRIDE + kj] = u;
    }
#pragma unroll
    for (int r = 0; r < 4; r++) {
      int i = t * 4 + r;
      int kr = i >> 5, c4 = (i & 31) * 4;
      uint2 u = *(const uint2*)&g_W1h[(k0 + kr) * 128 + c4];
      *(uint2*)&Bs[kr * BS_STRIDE + c4] = u;
    }
    __syncthreads();
#pragma unroll
    for (int kk = 0; kk < 32; kk += 16) {
      unsigned int a0, a1, a2, a3;
      {
        unsigned int addr = (unsigned int)__cvta_generic_to_shared(
            &As[(warp_m * 16 + (lane & 15)) * AS_STRIDE + kk + ((lane >> 4) << 3)]);
        asm volatile("ldmatrix.sync.aligned.m8n8.x4.shared.b16 {%0,%1,%2,%3}, [%4];"
                     : "=r"(a0), "=r"(a1), "=r"(a2), "=r"(a3) : "r"(addr));
      }
#pragma unroll
      for (int tp = 0; tp < 4; tp++) {
        unsigned int b0, b1, b2, b3;
        unsigned int addr = (unsigned int)__cvta_generic_to_shared(
            &Bs[(kk + (lane & 15)) * BS_STRIDE + warp_n * 64 + tp * 16 + ((lane >> 4) << 3)]);
        asm volatile("ldmatrix.sync.aligned.m8n8.x4.trans.shared.b16 {%0,%1,%2,%3}, [%4];"
                     : "=r"(b0), "=r"(b1), "=r"(b2), "=r"(b3) : "r"(addr));
        asm volatile("mma.sync.aligned.m16n8k16.row.col.f32.f16.f16.f32 "
                     "{%0,%1,%2,%3}, {%4,%5,%6,%7}, {%8,%9}, {%0,%1,%2,%3};"
                     : "+f"(acc[2 * tp][0]), "+f"(acc[2 * tp][1]),
                       "+f"(acc[2 * tp][2]), "+f"(acc[2 * tp][3])
                     : "r"(a0), "r"(a1), "r"(a2), "r"(a3), "r"(b0), "r"(b1));
        asm volatile("mma.sync.aligned.m16n8k16.row.col.f32.f16.f16.f32 "
                     "{%0,%1,%2,%3}, {%4,%5,%6,%7}, {%8,%9}, {%0,%1,%2,%3};"
                     : "+f"(acc[2 * tp + 1][0]), "+f"(acc[2 * tp + 1][1]),
                       "+f"(acc[2 * tp + 1][2]), "+f"(acc[2 * tp + 1][3])
                     : "r"(a0), "r"(a1), "r"(a2), "r"(a3), "r"(b2), "r"(b3));
      }
    }
    __syncthreads();
  }
#pragma unroll
  for (int nt = 0; nt < 8; nt++) {
    int c0 = warp_n * 64 + nt * 8 + (lane & 3) * 2;
    int r0 = warp_m * 16 + (lane >> 2);
    __half2 lo = __floats2half2_rn(acc[nt][0], acc[nt][1]);
    __half2 hi = __floats2half2_rn(acc[nt][2], acc[nt][3]);
    *(__half2*)&Hs[r0 * HS_STRIDE + c0] = lo;
    *(__half2*)&Hs[(r0 + 8) * HS_STRIDE + c0] = hi;
  }
  __syncthreads();
  float4 av = *(const float4*)&a_s[lane * 4];
  float4 dv = *(const float4*)&a_d[lane * 4];
#pragma unroll
  for (int j = 0; j < 8; j++) {
    int n = wid * 8 + j;
    int nd = node0 + n;
    uint2 u = *(uint2*)&Hs[n * HS_STRIDE + lane * 4];
    float2 f0 = __half22float2(*(const __half2*)&u.x);
    float2 f1 = __half22float2(*(const __half2*)&u.y);
    if (nd < NN) *(uint2*)&g_h1h[(long long)nd * 128 + lane * 4] = u;
    float ps = f0.x * av.x + f0.y * av.y + f1.x * av.z + f1.y * av.w;
    float pd = f0.x * dv.x + f0.y * dv.y + f1.x * dv.z + f1.y * dv.w;
#pragma unroll
    for (int o = 4; o > 0; o >>= 1) {
      ps += __shfl_xor_sync(0xffffffffu, ps, o);
      pd += __shfl_xor_sync(0xffffffffu, pd, o);
    }
    if ((lane & 7) == 0 && nd < NN) {
      g_as1[nd * 4 + (lane >> 3)] = ps;
      g_ad1[nd * 4 + (lane >> 3)] = pd;
    }
  }
}

// ---------------- layer1 fused softmax+aggregate (64-thr blocks) ----------------
__global__ __launch_bounds__(64) void k_agg1(const float* __restrict__ b1) {
  __shared__ int   sm_s[2][32];
  __shared__ float sm_e[2][4][32];
  int wip = threadIdx.x >> 5;
  int node = blockIdx.x * 2 + wip;
  int lane = threadIdx.x & 31;
  if (node >= NN) return;
  int beg = g_rowptr[node], end = g_rowptr[node + 1];
  float4 adv = *(const float4*)&g_ad1[node * 4];
  int head = lane >> 3;
  float acc0 = 0, acc1 = 0, acc2 = 0, acc3 = 0, den = 0;
  for (int base = beg; base < end; base += 32) {
    int i = base + lane;
    if (i < end) {
      int s = g_srcidx[i];
      float4 asv = *(const float4*)&g_as1[s * 4];
      float t0 = asv.x + adv.x; t0 = t0 > 0.f ? t0 : 0.2f * t0;
      float t1 = asv.y + adv.y; t1 = t1 > 0.f ? t1 : 0.2f * t1;
      float t2 = asv.z + adv.z; t2 = t2 > 0.f ? t2 : 0.2f * t2;
      float t3 = asv.w + adv.w; t3 = t3 > 0.f ? t3 : 0.2f * t3;
      sm_s[wip][lane] = s;
      sm_e[wip][0][lane] = __expf(t0);
      sm_e[wip][1][lane] = __expf(t1);
      sm_e[wip][2][lane] = __expf(t2);
      sm_e[wip][3][lane] = __expf(t3);
    }
    __syncwarp();
    int cnt = min(32, end - base);
    int k = 0;
    for (; k + 4 <= cnt; k += 4) {
      int4   ss = *(const int4*)&sm_s[wip][k];
      float4 ww = *(const float4*)&sm_e[wip][head][k];
      uint2 u0 = *((const uint2*)(g_h1h + (long long)ss.x * 128) + lane);
      uint2 u1 = *((const uint2*)(g_h1h + (long long)ss.y * 128) + lane);
      uint2 u2 = *((const uint2*)(g_h1h + (long long)ss.z * 128) + lane);
      uint2 u3 = *((const uint2*)(g_h1h + (long long)ss.w * 128) + lane);
      float2 a0 = __half22float2(*(const __half2*)&u0.x);
      float2 b0 = __half22float2(*(const __half2*)&u0.y);
      float2 a1 = __half22float2(*(const __half2*)&u1.x);
      float2 b1v = __half22float2(*(const __half2*)&u1.y);
      float2 a2 = __half22float2(*(const __half2*)&u2.x);
      float2 b2v = __half22float2(*(const __half2*)&u2.y);
      float2 a3 = __half22float2(*(const __half2*)&u3.x);
      float2 b3v = __half22float2(*(const __half2*)&u3.y);
      acc0 = fmaf(ww.x, a0.x, acc0); acc1 = fmaf(ww.x, a0.y, acc1);
      acc2 = fmaf(ww.x, b0.x, acc2); acc3 = fmaf(ww.x, b0.y, acc3);
      acc0 = fmaf(ww.y, a1.x, acc0); acc1 = fmaf(ww.y, a1.y, acc1);
      acc2 = fmaf(ww.y, b1v.x, acc2); acc3 = fmaf(ww.y, b1v.y, acc3);
      acc0 = fmaf(ww.z, a2.x, acc0); acc1 = fmaf(ww.z, a2.y, acc1);
      acc2 = fmaf(ww.z, b2v.x, acc2); acc3 = fmaf(ww.z, b2v.y, acc3);
      acc0 = fmaf(ww.w, a3.x, acc0); acc1 = fmaf(ww.w, a3.y, acc1);
      acc2 = fmaf(ww.w, b3v.x, acc2); acc3 = fmaf(ww.w, b3v.y, acc3);
      den += (ww.x + ww.y) + (ww.z + ww.w);
    }
    for (; k < cnt; k++) {
      int s = sm_s[wip][k];
      float w = sm_e[wip][head][k];
      uint2 u = *((const uint2*)(g_h1h + (long long)s * 128) + lane);
      float2 f0 = __half22float2(*(const __half2*)&u.x);
      float2 f1 = __half22float2(*(const __half2*)&u.y);
      acc0 = fmaf(w, f0.x, acc0);
      acc1 = fmaf(w, f0.y, acc1);
      acc2 = fmaf(w, f1.x, acc2);
      acc3 = fmaf(w, f1.y, acc3);
      den += w;
    }
    __syncwarp();
  }
  float inv = 1.0f / den;
  int c0 = lane * 4;
  float v0 = acc0 * inv + b1[c0];
  float v1 = acc1 * inv + b1[c0 + 1];
  float v2 = acc2 * inv + b1[c0 + 2];
  float v3 = acc3 * inv + b1[c0 + 3];
  v0 = v0 > 0.f ? v0 : expm1f(v0);
  v1 = v1 > 0.f ? v1 : expm1f(v1);
  v2 = v2 > 0.f ? v2 : expm1f(v2);
  v3 = v3 > 0.f ? v3 : expm1f(v3);
  __half2 h0 = __floats2half2_rn(v0, v1);
  __half2 h1 = __floats2half2_rn(v2, v3);
  uint2 st;
  st.x = *(unsigned int*)&h0;
  st.y = *(unsigned int*)&h1;
  *((uint2*)(g_x2h + (long long)node * 128) + lane) = st;
}

// ---------------- layer2 linear ----------------
__global__ __launch_bounds__(256) void k_gemm2(
    const float* __restrict__ W2, const float* __restrict__ a_s,
    const float* __restrict__ a_d) {
  __shared__ float xsT2[128][36];
  int t = threadIdx.x;
  int node0 = blockIdx.x * 32;
  for (int i = t; i < 32 * 64; i += 256) {
    int m = i >> 6, k2 = i & 63;
    int nd = node0 + m;
    float2 f = (nd < NN)
        ? __half22float2(*((const __half2*)(g_x2h + (long long)nd * 128) + k2))
        : make_float2(0.f, 0.f);
    xsT2[2 * k2][m] = f.x;
    xsT2[2 * k2 + 1][m] = f.y;
  }
  __syncthreads();
  int c = t & 31;
  int g = t >> 5;
  float acc[4] = {0.f, 0.f, 0.f, 0.f};
#pragma unroll 8
  for (int k = 0; k < 128; k++) {
    float w = W2[k * 32 + c];
    float4 xv = *(const float4*)&xsT2[k][4 * g];
    acc[0] = fmaf(xv.x, w, acc[0]);
    acc[1] = fmaf(xv.y, w, acc[1]);
    acc[2] = fmaf(xv.z, w, acc[2]);
    acc[3] = fmaf(xv.w, w, acc[3]);
  }
  float asv = a_s[c], adv = a_d[c];
#pragma unroll
  for (int j = 0; j < 4; j++) {
    int nd = node0 + 4 * g + j;
    if (nd >= NN) continue;
    g_h2h[nd * 32 + c] = __float2half_rn(acc[j]);
    float ps = acc[j] * asv;
    float pd = acc[j] * adv;
#pragma unroll
    for (int o = 16; o > 0; o >>= 1) {
      ps += __shfl_xor_sync(0xffffffffu, ps, o);
      pd += __shfl_xor_sync(0xffffffffu, pd, o);
    }
    if (c == 0) { g_as2[nd] = ps; g_ad2[nd] = pd; }
  }
}

// ---------------- layer2 fused softmax+aggregate + pool (64-thr blocks) ----------------
__global__ __launch_bounds__(64) void k_agg2(const float* __restrict__ b2,
                                             const void* batch) {
  __shared__ int   sm_s[2][32];
  __shared__ float sm_e[2][32];
  int wip = threadIdx.x >> 5;
  int node = blockIdx.x * 2 + wip;
  int lane = threadIdx.x & 31;
  if (node >= NN) return;
  int beg = g_rowptr[node], end = g_rowptr[node + 1];
  float adv = g_ad2[node];
  float acc = 0.f, den = 0.f;
  for (int base = beg; base < end; base += 32) {
    int i = base + lane;
    if (i < end) {
      int s = g_srcidx[i];
      float a = g_as2[s] + adv;
      a = a > 0.f ? a : 0.2f * a;
      sm_s[wip][lane] = s;
      sm_e[wip][lane] = __expf(a);
    }
    __syncwarp();
    int cnt = min(32, end - base);
    int k = 0;
    for (; k + 4 <= cnt; k += 4) {
      int4   ss = *(const int4*)&sm_s[wip][k];
      float4 ww = *(const float4*)&sm_e[wip][k];
      __half h0 = g_h2h[ss.x * 32 + lane];
      __half h1 = g_h2h[ss.y * 32 + lane];
      __half h2 = g_h2h[ss.z * 32 + lane];
      __half h3 = g_h2h[ss.w * 32 + lane];
      acc = fmaf(ww.x, __half2float(h0), acc);
      acc = fmaf(ww.y, __half2float(h1), acc);
      acc = fmaf(ww.z, __half2float(h2), acc);
      acc = fmaf(ww.w, __half2float(h3), acc);
      den += (ww.x + ww.y) + (ww.z + ww.w);
    }
    for (; k < cnt; k++) {
      float w = sm_e[wip][k];
      acc = fmaf(w, __half2float(g_h2h[sm_s[wip][k] * 32 + lane]), acc);
      den += w;
    }
    __syncwarp();
  }
  float v = acc / den + b2[lane];
  v = v > 0.f ? v : expm1f(v);
  int gph = idx_at(batch, g_is64, node);
  atomicAdd(&g_pooled[gph * 32 + lane], v);
}

// ---------------- classifier + state reset ----------------
__global__ void k_cls(const float* __restrict__ Wc1, const float* __restrict__ bc1,
                      const float* __restrict__ Wc2, const float* __restrict__ bc2,
                      float* __restrict__ out) {
  int i = blockIdx.x * blockDim.x + threadIdx.x;
  if (i < NN) g_deg[i] = 0;
  if (i >= GG) return;
  int g = i;
  float inv = 1.0f / g_cnt[g];
  float p[32];
#pragma unroll
  for (int c = 0; c < 32; c++) {
    p[c] = g_pooled[g * 32 + c] * inv;
    g_pooled[g * 32 + c] = 0.f;
  }
  g_cnt[g] = 0.f;
  float o = bc2[0];
#pragma unroll
  for (int j = 0; j < 16; j++) {
    float z = bc1[j];
#pragma unroll
    for (int c = 0; c < 32; c++) z = fmaf(p[c], Wc1[c * 16 + j], z);
    if (z > 0.f) o = fmaf(z, Wc2[j], o);
  }
  out[g] = o;
}

// ---------------- launch ----------------
extern "C" void kernel_launch(void* const* d_in, const int* in_sizes, int n_in,
                              void* d_out, int out_size) {
  const float* x   = (const float*)d_in[0];
  const void*  ei  = d_in[1];
  const void*  bat = d_in[3];
  const float* W1  = (const float*)d_in[4];
  const float* as1 = (const float*)d_in[5];
  const float* ad1 = (const float*)d_in[6];
  const float* b1  = (const float*)d_in[7];
  const float* W2  = (const float*)d_in[8];
  const float* as2 = (const float*)d_in[9];
  const float* ad2 = (const float*)d_in[10];
  const float* b2  = (const float*)d_in[11];
  const float* Wc1 = (const float*)d_in[12];
  const float* bc1 = (const float*)d_in[13];
  const float* Wc2 = (const float*)d_in[14];
  const float* bc2 = (const float*)d_in[15];
  float* out = (float*)d_out;

  k_count<<<(HE + NN + 255) / 256 + CVTB, 256>>>(ei, bat, W1);
  k_blockscan<<<NB, 256>>>();
  k_rowptr<<<NB, 256>>>();
  k_gs<<<GB1 + SCB, 256>>>(x, as1, ad1, ei);       // 4th launch -> ncu window
  k_agg1<<<(NN + 1) / 2, 64>>>(b1);
  k_gemm2<<<(NN + 31) / 32, 256>>>(W2, as2, ad2);
  k_agg2<<<(NN + 1) / 2, 64>>>(b2, bat);
  k_cls<<<NB, 256>>>(Wc1, bc1, Wc2, bc2, out);
}